// round 4
// baseline (speedup 1.0000x reference)
#include <cuda_runtime.h>
#include <cuda_fp16.h>

// Problem constants
#define T_TOTAL 4096
#define LAYERS  8
#define HIDDEN  1024
#define G4      4096
#define LETTERS 100
#define NCTA    128
#define TPB     256
#define NCELLS  (T_TOTAL * LAYERS)   // 32768

// ---------------------------------------------------------------------------
// Device scratch
// ---------------------------------------------------------------------------
__device__ float g_gin[(size_t)T_TOTAL * LAYERS * G4];          // 512 MB input projections
__device__ __half g_w2[(size_t)LAYERS * NCTA * 32 * HIDDEN];    // 64 MB fp16 repacked W_hh
__device__ __align__(16) float g_h[2][HIDDEN];                  // ping-pong hidden state
__device__ __align__(16) float g_c[HIDDEN];                     // final cell state
__device__ int g_flags[NCTA * 32];                              // per-CTA flag, 128B padded

__device__ __forceinline__ int ld_acquire_s32(const int* p) {
    int v;
    asm volatile("ld.acquire.gpu.global.u32 %0, [%1];" : "=r"(v) : "l"(p) : "memory");
    return v;
}
__device__ __forceinline__ void st_release_s32(int* p, int v) {
    asm volatile("st.release.gpu.global.u32 [%0], %1;" :: "l"(p), "r"(v) : "memory");
}
__device__ __forceinline__ float tanh_approx(float x) {
    float y;
    asm("tanh.approx.f32 %0, %1;" : "=f"(y) : "f"(x));
    return y;
}
__device__ __forceinline__ float sigmoid_fast(float x) {
    return 0.5f + 0.5f * tanh_approx(0.5f * x);
}
__device__ __forceinline__ void dot8(float& acc, uint4 wv, float4 hA, float4 hB) {
    const __half2* hp = (const __half2*)&wv;
    float2 f0 = __half22float2(hp[0]);
    float2 f1 = __half22float2(hp[1]);
    float2 f2 = __half22float2(hp[2]);
    float2 f3 = __half22float2(hp[3]);
    acc += f0.x * hA.x + f0.y * hA.y;
    acc += f1.x * hA.z + f1.y * hA.w;
    acc += f2.x * hB.x + f2.y * hB.y;
    acc += f3.x * hB.z + f3.y * hB.w;
}

// ---------------------------------------------------------------------------
// Phase 1a: gin[cell][row] = W_ih@x_t + b_ih + b_hh; reset state/flags.
// ---------------------------------------------------------------------------
__global__ void precompute_kernel(const float* __restrict__ website,
                                  const float* __restrict__ payload,
                                  const float* __restrict__ W_ih,
                                  const float* __restrict__ b_ih,
                                  const float* __restrict__ b_hh) {
    __shared__ float Xsm[16 * LETTERS];
    const int rt = blockIdx.x;
    const int l  = blockIdx.y;
    const int t0 = blockIdx.z * 16;

    for (int idx = threadIdx.x; idx < 16 * LETTERS; idx += 128) {
        int tt = idx / LETTERS, k = idx % LETTERS;
        int t = t0 + tt;
        Xsm[idx] = (t < 2048) ? website[t * LETTERS + k]
                              : payload[(t - 2048) * LETTERS + k];
    }
    __syncthreads();

    const int row = rt * 128 + threadIdx.x;
    const float* wp = W_ih + ((size_t)l * G4 + row) * LETTERS;

    float acc[16];
#pragma unroll
    for (int tt = 0; tt < 16; tt++) acc[tt] = 0.0f;
    for (int k = 0; k < LETTERS; k++) {
        float w = __ldg(wp + k);
#pragma unroll
        for (int tt = 0; tt < 16; tt++) acc[tt] += w * Xsm[tt * LETTERS + k];
    }
    const float bias = b_ih[l * G4 + row] + b_hh[l * G4 + row];
#pragma unroll
    for (int tt = 0; tt < 16; tt++) {
        size_t idx = (((size_t)(t0 + tt)) * LAYERS + l) * G4 + row;
        g_gin[idx] = acc[tt] + bias;
    }

    if (blockIdx.x == 0 && blockIdx.y == 0 && blockIdx.z == 0) {
        for (int i = threadIdx.x; i < HIDDEN; i += 128) {
            g_h[0][i] = 0.0f;
            g_h[1][i] = 0.0f;
        }
        for (int i = threadIdx.x; i < NCTA * 32; i += 128) g_flags[i] = 0;
    }
}

// ---------------------------------------------------------------------------
// Phase 1b: repack W_hh fp32 [l][row][k] -> fp16 (R2 layout, verified).
// ---------------------------------------------------------------------------
__global__ void repack_whh_kernel(const float* __restrict__ W_hh) {
    size_t idx = (size_t)blockIdx.x * 1024 + threadIdx.x;   // over 8*4096*1024
    int k = (int)(idx & 1023);
    size_t rowl = idx >> 10;
    int row = (int)(rowl & 4095);
    int l   = (int)(rowl >> 12);
    int g = row >> 10, rem = row & 1023, bb = rem >> 3, j = rem & 7;
    int r = g * 8 + j;
    int it = k >> 8;
    int part = (k & 255) >> 7;
    int lane = (k & 127) >> 2;
    int q = part * 4 + (k & 3);
    int off = (it * 32 + lane) * 8 + q;
    g_w2[((((size_t)l * NCTA) + bb) * 32 + r) * HIDDEN + off] = __float2half(W_hh[idx]);
}

// ---------------------------------------------------------------------------
// Phase 2: persistent recurrent kernel, double-buffered weight pipeline.
// 128 CTAs x 256 threads; warp w computes rows 4w..4w+3 (ridx = gate*8 + j).
// ---------------------------------------------------------------------------

#define PREFETCH_W(DST, CELL) do {                                            \
    const uint4* _wrow = wbase0 + (size_t)((CELL) & 7) * layer_stride_u4;     \
    _Pragma("unroll")                                                         \
    for (int _r = 0; _r < 4; _r++)                                            \
        _Pragma("unroll")                                                     \
        for (int _it = 0; _it < 4; _it++)                                     \
            DST[_r * 4 + _it] = __ldg(&_wrow[(size_t)_r * 128 + _it * 32 + lane]); \
} while (0)

#define PREFETCH_GIN(SLOT, CELL) do {                                         \
    if (tid < 32)                                                             \
        gin_sm[SLOT][tid] = __ldcs(&g_gin[(size_t)(CELL) * G4                 \
                                          + (tid >> 3) * HIDDEN + bb * 8 + (tid & 7)]); \
} while (0)

#define DO_CELL(CELL, WREG, SLOT) do {                                        \
    const int _cell = (CELL);                                                 \
    if (tid < NCTA) {                                                         \
        const int* _fp = &g_flags[tid * 32];                                  \
        while (ld_acquire_s32(_fp) < _cell) { }                               \
    }                                                                         \
    __syncthreads();                                                          \
    ((float4*)h_sm)[tid] = __ldcg(&((const float4*)g_h[_cell & 1])[tid]);     \
    __syncthreads();                                                          \
    float acc0 = 0.f, acc1 = 0.f, acc2 = 0.f, acc3 = 0.f;                     \
    _Pragma("unroll")                                                         \
    for (int _it = 0; _it < 4; _it++) {                                       \
        float4 _hA = *(const float4*)&h_sm[_it * 256 + lane * 4];             \
        float4 _hB = *(const float4*)&h_sm[_it * 256 + 128 + lane * 4];       \
        dot8(acc0, WREG[0 * 4 + _it], _hA, _hB);                              \
        dot8(acc1, WREG[1 * 4 + _it], _hA, _hB);                              \
        dot8(acc2, WREG[2 * 4 + _it], _hA, _hB);                              \
        dot8(acc3, WREG[3 * 4 + _it], _hA, _hB);                              \
    }                                                                         \
    _Pragma("unroll")                                                         \
    for (int _s = 16; _s > 0; _s >>= 1) {                                     \
        acc0 += __shfl_xor_sync(0xffffffffu, acc0, _s);                       \
        acc1 += __shfl_xor_sync(0xffffffffu, acc1, _s);                       \
        acc2 += __shfl_xor_sync(0xffffffffu, acc2, _s);                       \
        acc3 += __shfl_xor_sync(0xffffffffu, acc3, _s);                       \
    }                                                                         \
    if (lane == 0) {                                                          \
        g_sm[w * 4 + 0] = acc0; g_sm[w * 4 + 1] = acc1;                       \
        g_sm[w * 4 + 2] = acc2; g_sm[w * 4 + 3] = acc3;                       \
    }                                                                         \
    __syncthreads();                                                          \
    if (tid < 8) {                                                            \
        float iv = sigmoid_fast(g_sm[tid]      + gin_sm[SLOT][tid]);          \
        float fv = sigmoid_fast(g_sm[8 + tid]  + gin_sm[SLOT][8 + tid]);      \
        float gv = tanh_approx (g_sm[16 + tid] + gin_sm[SLOT][16 + tid]);     \
        float ov = sigmoid_fast(g_sm[24 + tid] + gin_sm[SLOT][24 + tid]);     \
        c = fv * c + iv * gv;                                                 \
        g_h[(_cell & 1) ^ 1][bb * 8 + tid] = ov * tanh_approx(c);             \
    }                                                                         \
    if (tid < 32) {                                                           \
        __syncwarp();                                                         \
        if (tid == 0) {                                                       \
            __threadfence();                                                  \
            st_release_s32(&g_flags[bb * 32], _cell + 1);                     \
        }                                                                     \
    }                                                                         \
} while (0)

__global__ void __launch_bounds__(TPB, 1)
lstm_kernel(const float* __restrict__ W_lin,
            const float* __restrict__ b_lin,
            const float* __restrict__ W_out,
            const float* __restrict__ b_out,
            float* __restrict__ out) {
    __shared__ __align__(16) float h_sm[HIDDEN];
    __shared__ float g_sm[32];
    __shared__ float gin_sm[2][32];
    __shared__ float feat_sm[16];

    const int tid  = threadIdx.x;
    const int bb   = blockIdx.x;
    const int w    = tid >> 5;
    const int lane = tid & 31;

    const uint4* __restrict__ wbase0 =
        (const uint4*)(g_w2 + (((size_t)bb) * 32 + w * 4) * HIDDEN);
    const size_t layer_stride_u4 = (size_t)NCTA * 32 * HIDDEN / 8;

    float c = 0.0f;   // thread tid<8 owns c[bb*8+tid]
    uint4 wA[16], wB[16];

    PREFETCH_W(wA, 0);
    PREFETCH_GIN(0, 0);

    for (int base = 0; base < NCELLS; base += 2) {
        // prefetch cell base+1 while cell base waits/computes
        PREFETCH_W(wB, base + 1);
        PREFETCH_GIN(1, base + 1);
        DO_CELL(base, wA, 0);

        // prefetch cell base+2 while cell base+1 waits/computes
        const int nx = (base + 2 < NCELLS) ? base + 2 : 0;
        PREFETCH_W(wA, nx);
        PREFETCH_GIN(0, nx);
        DO_CELL(base + 1, wB, 1);
    }

    // ---- publish final c, final flag round, epilogue on CTA 0 ----
    if (tid < 8) g_c[bb * 8 + tid] = c;
    if (tid < 32) {
        __syncwarp();
        if (tid == 0) {
            __threadfence();
            st_release_s32(&g_flags[bb * 32], NCELLS + 1);
        }
    }

    if (bb == 0) {
        if (tid < NCTA) {
            while (ld_acquire_s32(&g_flags[tid * 32]) < NCELLS + 1) { }
        }
        __syncthreads();
        if (tid < 16) {
            const float* wl = W_lin + tid * HIDDEN;
            float a = b_lin[tid];
            for (int k = 0; k < HIDDEN; k++) a += wl[k] * __ldcg(&g_c[k]);
            feat_sm[tid] = a;
        }
        __syncthreads();
        if (tid == 0) {
            float sum = b_out[0];
#pragma unroll
            for (int k = 0; k < 16; k++) sum += W_out[k] * feat_sm[k];
            out[0] = 1.0f / (1.0f + expf(-sum));
        }
    }
}

// ---------------------------------------------------------------------------
// Harness entry. Inputs: 0 website, 1 payload, 2 W_ih, 3 W_hh, 4 b_ih,
// 5 b_hh, 6 W_lin, 7 b_lin, 8 W_out, 9 b_out
// ---------------------------------------------------------------------------
extern "C" void kernel_launch(void* const* d_in, const int* in_sizes, int n_in,
                              void* d_out, int out_size) {
    const float* website = (const float*)d_in[0];
    const float* payload = (const float*)d_in[1];
    const float* W_ih    = (const float*)d_in[2];
    const float* W_hh    = (const float*)d_in[3];
    const float* b_ih    = (const float*)d_in[4];
    const float* b_hh    = (const float*)d_in[5];
    const float* W_lin   = (const float*)d_in[6];
    const float* b_lin   = (const float*)d_in[7];
    const float* W_out   = (const float*)d_in[8];
    const float* b_out   = (const float*)d_in[9];
    float* out = (float*)d_out;

    dim3 grid1(32, 8, 256);
    precompute_kernel<<<grid1, 128>>>(website, payload, W_ih, b_ih, b_hh);
    repack_whh_kernel<<<(LAYERS * G4 * HIDDEN) / 1024, 1024>>>(W_hh);
    lstm_kernel<<<NCTA, TPB>>>(W_lin, b_lin, W_out, b_out, out);
}

// round 5
// speedup vs baseline: 1.5532x; 1.5532x over previous
#include <cuda_runtime.h>
#include <cuda_fp16.h>

// Problem constants
#define T_TOTAL 4096
#define LAYERS  8
#define HIDDEN  1024
#define G4      4096
#define LETTERS 100
#define NCTA    128
#define TPB     256
#define NCELLS  (T_TOTAL * LAYERS)   // 32768
#define SMEM_LAYERS 3                // layers 0..2 resident in shared memory
#define WSMEM_BYTES (SMEM_LAYERS * 32 * HIDDEN * 2)   // 196608

// ---------------------------------------------------------------------------
// Device scratch
// ---------------------------------------------------------------------------
__device__ float g_gin[(size_t)T_TOTAL * LAYERS * G4];          // 512 MB input projections
__device__ __half g_w2[(size_t)LAYERS * NCTA * 32 * HIDDEN];    // 64 MB fp16 repacked W_hh
__device__ __align__(16) float g_h[2][HIDDEN];                  // ping-pong hidden state
__device__ __align__(16) float g_c[HIDDEN];                     // final cell state
__device__ unsigned g_ctr;                                      // barrier generation counter

__device__ __forceinline__ unsigned ld_acquire_u32(const unsigned* p) {
    unsigned v;
    asm volatile("ld.acquire.gpu.global.u32 %0, [%1];" : "=r"(v) : "l"(p) : "memory");
    return v;
}
__device__ __forceinline__ void red_release_add(unsigned* p, unsigned v) {
    asm volatile("red.release.gpu.global.add.u32 [%0], %1;" :: "l"(p), "r"(v) : "memory");
}
__device__ __forceinline__ float tanh_approx(float x) {
    float y;
    asm("tanh.approx.f32 %0, %1;" : "=f"(y) : "f"(x));
    return y;
}
__device__ __forceinline__ float sigmoid_fast(float x) {
    return 0.5f + 0.5f * tanh_approx(0.5f * x);
}
__device__ __forceinline__ void dot8(float& acc, uint4 wv, float4 hA, float4 hB) {
    const __half2* hp = (const __half2*)&wv;
    float2 f0 = __half22float2(hp[0]);
    float2 f1 = __half22float2(hp[1]);
    float2 f2 = __half22float2(hp[2]);
    float2 f3 = __half22float2(hp[3]);
    acc += f0.x * hA.x + f0.y * hA.y;
    acc += f1.x * hA.z + f1.y * hA.w;
    acc += f2.x * hB.x + f2.y * hB.y;
    acc += f3.x * hB.z + f3.y * hB.w;
}

// ---------------------------------------------------------------------------
// Phase 1a: gin[cell][row] = W_ih@x_t + b_ih + b_hh; reset state/counter.
// ---------------------------------------------------------------------------
__global__ void precompute_kernel(const float* __restrict__ website,
                                  const float* __restrict__ payload,
                                  const float* __restrict__ W_ih,
                                  const float* __restrict__ b_ih,
                                  const float* __restrict__ b_hh) {
    __shared__ float Xsm[16 * LETTERS];
    const int rt = blockIdx.x;
    const int l  = blockIdx.y;
    const int t0 = blockIdx.z * 16;

    for (int idx = threadIdx.x; idx < 16 * LETTERS; idx += 128) {
        int tt = idx / LETTERS, k = idx % LETTERS;
        int t = t0 + tt;
        Xsm[idx] = (t < 2048) ? website[t * LETTERS + k]
                              : payload[(t - 2048) * LETTERS + k];
    }
    __syncthreads();

    const int row = rt * 128 + threadIdx.x;
    const float* wp = W_ih + ((size_t)l * G4 + row) * LETTERS;

    float acc[16];
#pragma unroll
    for (int tt = 0; tt < 16; tt++) acc[tt] = 0.0f;
    for (int k = 0; k < LETTERS; k++) {
        float w = __ldg(wp + k);
#pragma unroll
        for (int tt = 0; tt < 16; tt++) acc[tt] += w * Xsm[tt * LETTERS + k];
    }
    const float bias = b_ih[l * G4 + row] + b_hh[l * G4 + row];
#pragma unroll
    for (int tt = 0; tt < 16; tt++) {
        size_t idx = (((size_t)(t0 + tt)) * LAYERS + l) * G4 + row;
        g_gin[idx] = acc[tt] + bias;
    }

    if (blockIdx.x == 0 && blockIdx.y == 0 && blockIdx.z == 0) {
        for (int i = threadIdx.x; i < HIDDEN; i += 128) {
            g_h[0][i] = 0.0f;
            g_h[1][i] = 0.0f;
        }
        if (threadIdx.x == 0) g_ctr = 0;
    }
}

// ---------------------------------------------------------------------------
// Phase 1b: repack W_hh fp32 [l][row][k] -> fp16 (R2 layout, verified).
// ---------------------------------------------------------------------------
__global__ void repack_whh_kernel(const float* __restrict__ W_hh) {
    size_t idx = (size_t)blockIdx.x * 1024 + threadIdx.x;   // over 8*4096*1024
    int k = (int)(idx & 1023);
    size_t rowl = idx >> 10;
    int row = (int)(rowl & 4095);
    int l   = (int)(rowl >> 12);
    int g = row >> 10, rem = row & 1023, bb = rem >> 3, j = rem & 7;
    int r = g * 8 + j;
    int it = k >> 8;
    int part = (k & 255) >> 7;
    int lane = (k & 127) >> 2;
    int q = part * 4 + (k & 3);
    int off = (it * 32 + lane) * 8 + q;
    g_w2[((((size_t)l * NCTA) + bb) * 32 + r) * HIDDEN + off] = __float2half(W_hh[idx]);
}

// ---------------------------------------------------------------------------
// Phase 2: persistent recurrent kernel. 128 CTAs x 256 threads.
// Warp w computes rows 4w..4w+3 (ridx = gate*8 + j). Layers 0..2 weights
// live in dynamic smem; layers 3..7 stream from L2 (prefetched pre-barrier).
// ---------------------------------------------------------------------------
__global__ void __launch_bounds__(TPB, 1)
lstm_kernel(const float* __restrict__ W_lin,
            const float* __restrict__ b_lin,
            const float* __restrict__ W_out,
            const float* __restrict__ b_out,
            float* __restrict__ out) {
    __shared__ __align__(16) float h_sm[HIDDEN];
    __shared__ float g_sm[32];
    __shared__ float gin_sm[32];
    __shared__ float hn_sm[8];
    __shared__ float feat_sm[16];
    extern __shared__ __align__(16) uint4 w_sm[];   // SMEM_LAYERS * 4096 uint4

    const int tid  = threadIdx.x;
    const int bb   = blockIdx.x;
    const int w    = tid >> 5;
    const int lane = tid & 31;

    // per-(layer) stride in uint4; this CTA+warp's base row group
    const size_t layer_stride_u4 = (size_t)NCTA * 32 * HIDDEN / 8;
    const uint4* __restrict__ wbase0 =
        (const uint4*)(g_w2 + (((size_t)bb) * 32 + w * 4) * HIDDEN);

    // ---- copy layers 0..2 of this CTA's weights into smem (once) ----
    {
        const uint4* src = (const uint4*)(g_w2 + ((size_t)bb) * 32 * HIDDEN);
        for (int l = 0; l < SMEM_LAYERS; l++) {
            const uint4* s = src + (size_t)l * layer_stride_u4;
#pragma unroll
            for (int i = tid; i < 4096; i += TPB)
                w_sm[l * 4096 + i] = __ldg(&s[i]);
        }
    }
    __syncthreads();

    float c = 0.0f;   // thread tid<8 owns c[bb*8+tid]

    for (int cell = 0; cell < NCELLS; cell++) {
        const int l = cell & 7;
        const bool local = (l < SMEM_LAYERS);
        uint4 wreg[16];

        // ---- global-weight prefetch (layers 3..7): issue before the barrier ----
        if (!local) {
            const uint4* wrow = wbase0 + (size_t)l * layer_stride_u4;
#pragma unroll
            for (int r = 0; r < 4; r++)
#pragma unroll
                for (int it = 0; it < 4; it++)
                    wreg[r * 4 + it] = __ldg(&wrow[(size_t)r * 128 + it * 32 + lane]);
        }

        // ---- gin prefetch (warp 0) ----
        if (tid < 32)
            gin_sm[tid] = __ldcs(&g_gin[(size_t)cell * G4
                                        + (tid >> 3) * HIDDEN + bb * 8 + (tid & 7)]);

        // ---- counter barrier: wait for all CTAs to have finished cell-1 ----
        if (tid == 0) {
            const unsigned target = (unsigned)NCTA * (unsigned)cell;
            while (ld_acquire_u32(&g_ctr) < target) { }
        }
        __syncthreads();

        // ---- load h (4KB, coalesced) ----
        ((float4*)h_sm)[tid] = __ldcg(&((const float4*)g_h[cell & 1])[tid]);
        __syncthreads();

        // ---- smem-resident weights (layers 0..2): conflict-free LDS.128 ----
        if (local) {
            const uint4* wrow = w_sm + l * 4096 + w * 512;
#pragma unroll
            for (int r = 0; r < 4; r++)
#pragma unroll
                for (int it = 0; it < 4; it++)
                    wreg[r * 4 + it] = wrow[r * 128 + it * 32 + lane];
        }

        // ---- 4 row dot-products per warp ----
        float acc0 = 0.f, acc1 = 0.f, acc2 = 0.f, acc3 = 0.f;
#pragma unroll
        for (int it = 0; it < 4; it++) {
            float4 hA = *(const float4*)&h_sm[it * 256 + lane * 4];
            float4 hB = *(const float4*)&h_sm[it * 256 + 128 + lane * 4];
            dot8(acc0, wreg[0 * 4 + it], hA, hB);
            dot8(acc1, wreg[1 * 4 + it], hA, hB);
            dot8(acc2, wreg[2 * 4 + it], hA, hB);
            dot8(acc3, wreg[3 * 4 + it], hA, hB);
        }
#pragma unroll
        for (int s = 16; s > 0; s >>= 1) {
            acc0 += __shfl_xor_sync(0xffffffffu, acc0, s);
            acc1 += __shfl_xor_sync(0xffffffffu, acc1, s);
            acc2 += __shfl_xor_sync(0xffffffffu, acc2, s);
            acc3 += __shfl_xor_sync(0xffffffffu, acc3, s);
        }
        if (lane == 0) {
            g_sm[w * 4 + 0] = acc0;
            g_sm[w * 4 + 1] = acc1;
            g_sm[w * 4 + 2] = acc2;
            g_sm[w * 4 + 3] = acc3;
        }
        __syncthreads();

        // ---- gates (8 threads of warp 0), coalesced h publish, arrive ----
        if (tid < 32) {
            if (tid < 8) {
                float iv = sigmoid_fast(g_sm[tid]      + gin_sm[tid]);
                float fv = sigmoid_fast(g_sm[8 + tid]  + gin_sm[8 + tid]);
                float gv = tanh_approx (g_sm[16 + tid] + gin_sm[16 + tid]);
                float ov = sigmoid_fast(g_sm[24 + tid] + gin_sm[24 + tid]);
                c = fv * c + iv * gv;
                hn_sm[tid] = ov * tanh_approx(c);
            }
            __syncwarp();
            if (tid == 0) {
                float4 a = *(const float4*)&hn_sm[0];
                float4 b = *(const float4*)&hn_sm[4];
                float4* dst = (float4*)&g_h[(cell & 1) ^ 1][bb * 8];
                dst[0] = a;
                dst[1] = b;
                red_release_add(&g_ctr, 1u);   // release orders the h stores
            }
        }
    }

    // ---- publish final c, arrive once more, epilogue on CTA 0 ----
    if (tid < 8) g_c[bb * 8 + tid] = c;
    if (tid < 32) {
        __syncwarp();
        if (tid == 0) red_release_add(&g_ctr, 1u);
    }

    if (bb == 0) {
        if (tid == 0) {
            const unsigned target = (unsigned)NCTA * (unsigned)(NCELLS + 1);
            while (ld_acquire_u32(&g_ctr) < target) { }
        }
        __syncthreads();
        if (tid < 16) {
            const float* wl = W_lin + tid * HIDDEN;
            float a = b_lin[tid];
            for (int k = 0; k < HIDDEN; k++) a += wl[k] * __ldcg(&g_c[k]);
            feat_sm[tid] = a;
        }
        __syncthreads();
        if (tid == 0) {
            float sum = b_out[0];
#pragma unroll
            for (int k = 0; k < 16; k++) sum += W_out[k] * feat_sm[k];
            out[0] = 1.0f / (1.0f + expf(-sum));
        }
    }
}

// ---------------------------------------------------------------------------
// Harness entry. Inputs: 0 website, 1 payload, 2 W_ih, 3 W_hh, 4 b_ih,
// 5 b_hh, 6 W_lin, 7 b_lin, 8 W_out, 9 b_out
// ---------------------------------------------------------------------------
extern "C" void kernel_launch(void* const* d_in, const int* in_sizes, int n_in,
                              void* d_out, int out_size) {
    const float* website = (const float*)d_in[0];
    const float* payload = (const float*)d_in[1];
    const float* W_ih    = (const float*)d_in[2];
    const float* W_hh    = (const float*)d_in[3];
    const float* b_ih    = (const float*)d_in[4];
    const float* b_hh    = (const float*)d_in[5];
    const float* W_lin   = (const float*)d_in[6];
    const float* b_lin   = (const float*)d_in[7];
    const float* W_out   = (const float*)d_in[8];
    const float* b_out   = (const float*)d_in[9];
    float* out = (float*)d_out;

    static int attr_set = 0;
    if (!attr_set) {
        cudaFuncSetAttribute(lstm_kernel,
                             cudaFuncAttributeMaxDynamicSharedMemorySize,
                             WSMEM_BYTES);
        attr_set = 1;
    }

    dim3 grid1(32, 8, 256);
    precompute_kernel<<<grid1, 128>>>(website, payload, W_ih, b_ih, b_hh);
    repack_whh_kernel<<<(LAYERS * G4 * HIDDEN) / 1024, 1024>>>(W_hh);
    lstm_kernel<<<NCTA, TPB, WSMEM_BYTES>>>(W_lin, b_lin, W_out, b_out, out);
}

// round 6
// speedup vs baseline: 1.6725x; 1.0768x over previous
#include <cuda_runtime.h>
#include <cuda_fp16.h>

// Problem constants
#define T_TOTAL 4096
#define LAYERS  8
#define HIDDEN  1024
#define G4      4096
#define LETTERS 100
#define NCTA    128
#define TPB     256
#define NCELLS  (T_TOTAL * LAYERS)   // 32768
#define SMEM_LAYERS 3                // layers 0..2 resident in shared memory
#define WSMEM_BYTES (SMEM_LAYERS * 32 * HIDDEN * 2)   // 196608
#define NLINES  8                    // barrier counter lines
#define CTAS_PER_LINE (NCTA / NLINES)   // 16

// ---------------------------------------------------------------------------
// Device scratch
// ---------------------------------------------------------------------------
__device__ float g_gin[(size_t)T_TOTAL * LAYERS * G4];          // 512 MB input projections
__device__ __half g_w2[(size_t)LAYERS * NCTA * 32 * HIDDEN];    // 64 MB fp16 repacked W_hh
__device__ __align__(16) float g_h[2][HIDDEN];                  // ping-pong hidden state
__device__ __align__(16) float g_c[HIDDEN];                     // final cell state

struct __align__(128) CtrLine { unsigned v; unsigned pad[31]; };
__device__ CtrLine g_ctrs[NLINES];                              // spread barrier counters

__device__ __forceinline__ unsigned ld_acquire_u32(const unsigned* p) {
    unsigned v;
    asm volatile("ld.acquire.gpu.global.u32 %0, [%1];" : "=r"(v) : "l"(p) : "memory");
    return v;
}
__device__ __forceinline__ void red_release_add(unsigned* p, unsigned v) {
    asm volatile("red.release.gpu.global.add.u32 [%0], %1;" :: "l"(p), "r"(v) : "memory");
}
__device__ __forceinline__ float tanh_approx(float x) {
    float y;
    asm("tanh.approx.f32 %0, %1;" : "=f"(y) : "f"(x));
    return y;
}
__device__ __forceinline__ float sigmoid_fast(float x) {
    return 0.5f + 0.5f * tanh_approx(0.5f * x);
}
__device__ __forceinline__ void dot8(float& acc, uint4 wv, float4 hA, float4 hB) {
    const __half2* hp = (const __half2*)&wv;
    float2 f0 = __half22float2(hp[0]);
    float2 f1 = __half22float2(hp[1]);
    float2 f2 = __half22float2(hp[2]);
    float2 f3 = __half22float2(hp[3]);
    acc += f0.x * hA.x + f0.y * hA.y;
    acc += f1.x * hA.z + f1.y * hA.w;
    acc += f2.x * hB.x + f2.y * hB.y;
    acc += f3.x * hB.z + f3.y * hB.w;
}

// ---------------------------------------------------------------------------
// Phase 1a: gin[cell][row] = W_ih@x_t + b_ih + b_hh; reset state/counters.
// ---------------------------------------------------------------------------
__global__ void precompute_kernel(const float* __restrict__ website,
                                  const float* __restrict__ payload,
                                  const float* __restrict__ W_ih,
                                  const float* __restrict__ b_ih,
                                  const float* __restrict__ b_hh) {
    __shared__ float Xsm[16 * LETTERS];
    const int rt = blockIdx.x;
    const int l  = blockIdx.y;
    const int t0 = blockIdx.z * 16;

    for (int idx = threadIdx.x; idx < 16 * LETTERS; idx += 128) {
        int tt = idx / LETTERS, k = idx % LETTERS;
        int t = t0 + tt;
        Xsm[idx] = (t < 2048) ? website[t * LETTERS + k]
                              : payload[(t - 2048) * LETTERS + k];
    }
    __syncthreads();

    const int row = rt * 128 + threadIdx.x;
    const float* wp = W_ih + ((size_t)l * G4 + row) * LETTERS;

    float acc[16];
#pragma unroll
    for (int tt = 0; tt < 16; tt++) acc[tt] = 0.0f;
    for (int k = 0; k < LETTERS; k++) {
        float w = __ldg(wp + k);
#pragma unroll
        for (int tt = 0; tt < 16; tt++) acc[tt] += w * Xsm[tt * LETTERS + k];
    }
    const float bias = b_ih[l * G4 + row] + b_hh[l * G4 + row];
#pragma unroll
    for (int tt = 0; tt < 16; tt++) {
        size_t idx = (((size_t)(t0 + tt)) * LAYERS + l) * G4 + row;
        g_gin[idx] = acc[tt] + bias;
    }

    if (blockIdx.x == 0 && blockIdx.y == 0 && blockIdx.z == 0) {
        for (int i = threadIdx.x; i < HIDDEN; i += 128) {
            g_h[0][i] = 0.0f;
            g_h[1][i] = 0.0f;
        }
        if (threadIdx.x < NLINES) g_ctrs[threadIdx.x].v = 0;
    }
}

// ---------------------------------------------------------------------------
// Phase 1b: repack W_hh fp32 [l][row][k] -> fp16 (R2 layout, verified).
// ---------------------------------------------------------------------------
__global__ void repack_whh_kernel(const float* __restrict__ W_hh) {
    size_t idx = (size_t)blockIdx.x * 1024 + threadIdx.x;   // over 8*4096*1024
    int k = (int)(idx & 1023);
    size_t rowl = idx >> 10;
    int row = (int)(rowl & 4095);
    int l   = (int)(rowl >> 12);
    int g = row >> 10, rem = row & 1023, bb = rem >> 3, j = rem & 7;
    int r = g * 8 + j;
    int it = k >> 8;
    int part = (k & 255) >> 7;
    int lane = (k & 127) >> 2;
    int q = part * 4 + (k & 3);
    int off = (it * 32 + lane) * 8 + q;
    g_w2[((((size_t)l * NCTA) + bb) * 32 + r) * HIDDEN + off] = __float2half(W_hh[idx]);
}

// ---------------------------------------------------------------------------
// Phase 2: persistent recurrent kernel. 128 CTAs x 256 threads.
// Warp w computes rows 4w..4w+3 (ridx = gate*8 + j). Layers 0..2 weights in
// dynamic smem; ALL weight fetches (LDS and LDG) issued before the barrier
// poll so they overlap the wait. Barrier is 8 spread counter lines.
// ---------------------------------------------------------------------------
__global__ void __launch_bounds__(TPB, 1)
lstm_kernel(const float* __restrict__ W_lin,
            const float* __restrict__ b_lin,
            const float* __restrict__ W_out,
            const float* __restrict__ b_out,
            float* __restrict__ out) {
    __shared__ __align__(16) float h_sm[HIDDEN];
    __shared__ float g_sm[32];
    __shared__ float gin_sm[32];
    __shared__ float hn_sm[8];
    __shared__ float feat_sm[16];
    extern __shared__ __align__(16) uint4 w_sm[];   // SMEM_LAYERS * 4096 uint4

    const int tid  = threadIdx.x;
    const int bb   = blockIdx.x;
    const int w    = tid >> 5;
    const int lane = tid & 31;

    const size_t layer_stride_u4 = (size_t)NCTA * 32 * HIDDEN / 8;
    const uint4* __restrict__ wbase0 =
        (const uint4*)(g_w2 + (((size_t)bb) * 32 + w * 4) * HIDDEN);
    unsigned* const my_ctr = &g_ctrs[bb & (NLINES - 1)].v;

    // ---- copy layers 0..2 of this CTA's weights into smem (once) ----
    {
        const uint4* src = (const uint4*)(g_w2 + ((size_t)bb) * 32 * HIDDEN);
        for (int l = 0; l < SMEM_LAYERS; l++) {
            const uint4* s = src + (size_t)l * layer_stride_u4;
#pragma unroll
            for (int i = tid; i < 4096; i += TPB)
                w_sm[l * 4096 + i] = __ldg(&s[i]);
        }
    }
    __syncthreads();

    float c = 0.0f;   // thread tid<8 owns c[bb*8+tid]

    for (int cell = 0; cell < NCELLS; cell++) {
        const int l = cell & 7;
        uint4 wreg[16];

        // ---- ALL weight fetches issued before the barrier (overlap wait) ----
        if (l < SMEM_LAYERS) {
            const uint4* wrow = w_sm + l * 4096 + w * 512;
#pragma unroll
            for (int r = 0; r < 4; r++)
#pragma unroll
                for (int it = 0; it < 4; it++)
                    wreg[r * 4 + it] = wrow[r * 128 + it * 32 + lane];
        } else {
            const uint4* wrow = wbase0 + (size_t)l * layer_stride_u4;
#pragma unroll
            for (int r = 0; r < 4; r++)
#pragma unroll
                for (int it = 0; it < 4; it++)
                    wreg[r * 4 + it] = __ldg(&wrow[(size_t)r * 128 + it * 32 + lane]);
        }

        // ---- gin prefetch (warp 0) ----
        if (tid < 32)
            gin_sm[tid] = __ldcs(&g_gin[(size_t)cell * G4
                                        + (tid >> 3) * HIDDEN + bb * 8 + (tid & 7)]);

        // ---- spread-counter barrier: 8 pollers, one line each ----
        if (tid < NLINES) {
            const unsigned target = (unsigned)CTAS_PER_LINE * (unsigned)cell;
            while (ld_acquire_u32(&g_ctrs[tid].v) < target) { }
        }
        __syncthreads();

        // ---- load h (4KB, coalesced) ----
        ((float4*)h_sm)[tid] = __ldcg(&((const float4*)g_h[cell & 1])[tid]);
        __syncthreads();

        // ---- 4 row dot-products per warp ----
        float acc0 = 0.f, acc1 = 0.f, acc2 = 0.f, acc3 = 0.f;
#pragma unroll
        for (int it = 0; it < 4; it++) {
            float4 hA = *(const float4*)&h_sm[it * 256 + lane * 4];
            float4 hB = *(const float4*)&h_sm[it * 256 + 128 + lane * 4];
            dot8(acc0, wreg[0 * 4 + it], hA, hB);
            dot8(acc1, wreg[1 * 4 + it], hA, hB);
            dot8(acc2, wreg[2 * 4 + it], hA, hB);
            dot8(acc3, wreg[3 * 4 + it], hA, hB);
        }
#pragma unroll
        for (int s = 16; s > 0; s >>= 1) {
            acc0 += __shfl_xor_sync(0xffffffffu, acc0, s);
            acc1 += __shfl_xor_sync(0xffffffffu, acc1, s);
            acc2 += __shfl_xor_sync(0xffffffffu, acc2, s);
            acc3 += __shfl_xor_sync(0xffffffffu, acc3, s);
        }
        if (lane == 0) {
            g_sm[w * 4 + 0] = acc0;
            g_sm[w * 4 + 1] = acc1;
            g_sm[w * 4 + 2] = acc2;
            g_sm[w * 4 + 3] = acc3;
        }
        __syncthreads();

        // ---- gates (8 threads of warp 0), coalesced h publish, arrive ----
        if (tid < 32) {
            if (tid < 8) {
                float iv = sigmoid_fast(g_sm[tid]      + gin_sm[tid]);
                float fv = sigmoid_fast(g_sm[8 + tid]  + gin_sm[8 + tid]);
                float gv = tanh_approx (g_sm[16 + tid] + gin_sm[16 + tid]);
                float ov = sigmoid_fast(g_sm[24 + tid] + gin_sm[24 + tid]);
                c = fv * c + iv * gv;
                hn_sm[tid] = ov * tanh_approx(c);
            }
            __syncwarp();
            if (tid == 0) {
                float4 a = *(const float4*)&hn_sm[0];
                float4 b = *(const float4*)&hn_sm[4];
                float4* dst = (float4*)&g_h[(cell & 1) ^ 1][bb * 8];
                dst[0] = a;
                dst[1] = b;
                red_release_add(my_ctr, 1u);   // release orders the h stores
            }
        }
    }

    // ---- publish final c, arrive once more, epilogue on CTA 0 ----
    if (tid < 8) g_c[bb * 8 + tid] = c;
    if (tid < 32) {
        __syncwarp();
        if (tid == 0) red_release_add(my_ctr, 1u);
    }

    if (bb == 0) {
        if (tid < NLINES) {
            const unsigned target = (unsigned)CTAS_PER_LINE * (unsigned)(NCELLS + 1);
            while (ld_acquire_u32(&g_ctrs[tid].v) < target) { }
        }
        __syncthreads();
        if (tid < 16) {
            const float* wl = W_lin + tid * HIDDEN;
            float a = b_lin[tid];
            for (int k = 0; k < HIDDEN; k++) a += wl[k] * __ldcg(&g_c[k]);
            feat_sm[tid] = a;
        }
        __syncthreads();
        if (tid == 0) {
            float sum = b_out[0];
#pragma unroll
            for (int k = 0; k < 16; k++) sum += W_out[k] * feat_sm[k];
            out[0] = 1.0f / (1.0f + expf(-sum));
        }
    }
}

// ---------------------------------------------------------------------------
// Harness entry. Inputs: 0 website, 1 payload, 2 W_ih, 3 W_hh, 4 b_ih,
// 5 b_hh, 6 W_lin, 7 b_lin, 8 W_out, 9 b_out
// ---------------------------------------------------------------------------
extern "C" void kernel_launch(void* const* d_in, const int* in_sizes, int n_in,
                              void* d_out, int out_size) {
    const float* website = (const float*)d_in[0];
    const float* payload = (const float*)d_in[1];
    const float* W_ih    = (const float*)d_in[2];
    const float* W_hh    = (const float*)d_in[3];
    const float* b_ih    = (const float*)d_in[4];
    const float* b_hh    = (const float*)d_in[5];
    const float* W_lin   = (const float*)d_in[6];
    const float* b_lin   = (const float*)d_in[7];
    const float* W_out   = (const float*)d_in[8];
    const float* b_out   = (const float*)d_in[9];
    float* out = (float*)d_out;

    static int attr_set = 0;
    if (!attr_set) {
        cudaFuncSetAttribute(lstm_kernel,
                             cudaFuncAttributeMaxDynamicSharedMemorySize,
                             WSMEM_BYTES);
        attr_set = 1;
    }

    dim3 grid1(32, 8, 256);
    precompute_kernel<<<grid1, 128>>>(website, payload, W_ih, b_ih, b_hh);
    repack_whh_kernel<<<(LAYERS * G4 * HIDDEN) / 1024, 1024>>>(W_hh);
    lstm_kernel<<<NCTA, TPB, WSMEM_BYTES>>>(W_lin, b_lin, W_out, b_out, out);
}